// round 14
// baseline (speedup 1.0000x reference)
#include <cuda_runtime.h>
#include <cuda_fp16.h>
#include <cstdint>

#define NR 65536
typedef __half fp16;

// ----------------------------- device scratch ------------------------------
__device__ float g_u[(size_t)NR * 1024];
__device__ fp16  g_cHi[(size_t)NR * 192];    // concat(z,f) padded to K=192
__device__ fp16  g_uHi[(size_t)NR * 1024];
__device__ fp16  g_hiA[(size_t)NR * 512];
__device__ fp16  g_loA[(size_t)NR * 512];
__device__ fp16  g_hiB[(size_t)NR * 512];
__device__ fp16  g_loB[(size_t)NR * 512];
__device__ float g_x[NR];
__device__ fp16  g_WhhHi[1536 * 512];
__device__ fp16  g_Wo1Hi[256 * 512];     // transposed [N=256, K=512], hi only
__device__ fp16  g_W2Hi[512 * 1024];     // transposed [N=512, K=1024]
__device__ fp16  g_W2Lo[512 * 1024];
__device__ fp16  g_W1Hi[1024 * 192];     // transposed+padded [N=1024, K=192]
__device__ fp16  g_W1Lo[1024 * 192];

// ----------------------------- small helpers -------------------------------
__device__ __forceinline__ float sig_(float x) { return 1.0f / (1.0f + expf(-x)); }
__device__ __forceinline__ float gelu_(float x) {
    return 0.5f * x * (1.0f + erff(x * 0.70710678f));
}
__device__ __forceinline__ uint32_t smem_u32(const void* p) {
    uint32_t a;
    asm("{ .reg .u64 t; cvta.to.shared.u64 t, %1; cvt.u32.u64 %0, t; }" : "=r"(a) : "l"(p));
    return a;
}
__device__ __forceinline__ uint32_t swz(uint32_t off) { return off ^ ((off >> 3) & 0x70); }

__device__ __forceinline__ void cpasync16(uint32_t saddr, const void* gptr) {
    asm volatile("{ .reg .u64 g; cvta.to.global.u64 g, %1; "
                 "cp.async.cg.shared.global [%0], [g], 16; }"
                 :: "r"(saddr), "l"(gptr) : "memory");
}
#define CP_COMMIT() asm volatile("cp.async.commit_group;" ::: "memory")
#define CP_WAIT1()  asm volatile("cp.async.wait_group 1;" ::: "memory")
#define CP_WAIT0()  asm volatile("cp.async.wait_group 0;" ::: "memory")

__device__ __forceinline__ void ldmx4(uint32_t* r, uint32_t addr) {
    asm volatile("ldmatrix.sync.aligned.m8n8.x4.shared.b16 {%0,%1,%2,%3}, [%4];"
        : "=r"(r[0]), "=r"(r[1]), "=r"(r[2]), "=r"(r[3]) : "r"(addr));
}
__device__ __forceinline__ void mma_fp16(float* d, const uint32_t* a, const uint32_t* b) {
    asm volatile("mma.sync.aligned.m16n8k16.row.col.f32.f16.f16.f32 "
        "{%0,%1,%2,%3}, {%4,%5,%6,%7}, {%8,%9}, {%0,%1,%2,%3};"
        : "+f"(d[0]), "+f"(d[1]), "+f"(d[2]), "+f"(d[3])
        : "r"(a[0]), "r"(a[1]), "r"(a[2]), "r"(a[3]), "r"(b[0]), "r"(b[1]));
}

// =========================== init-path kernels =============================
__global__ void k_prep(const float* __restrict__ z, const float* __restrict__ f) {
    size_t i = (size_t)blockIdx.x * blockDim.x + threadIdx.x;
    if (i >= (size_t)NR * 192) return;
    int row = (int)(i / 192), col = (int)(i % 192);
    float x = (col < 128) ? z[(size_t)row * 128 + col]
            : (col < 160) ? f[(size_t)row * 32 + col - 128] : 0.f;
    g_cHi[i] = __float2half_rn(x);
}

__global__ __launch_bounds__(256) void k_lngelu(
    const float* __restrict__ g1, const float* __restrict__ be1)
{
    const size_t row = blockIdx.x;
    const int tid = threadIdx.x, lane = tid & 31, w = tid >> 5;
    const float* up = g_u + row * 1024 + tid * 4;
    float4 v = *(const float4*)up;
    __shared__ float red[8];
    float s = v.x + v.y + v.z + v.w;
#pragma unroll
    for (int m = 16; m >= 1; m >>= 1) s += __shfl_xor_sync(~0u, s, m);
    if (lane == 0) red[w] = s;
    __syncthreads();
    float tot = 0.f;
#pragma unroll
    for (int i = 0; i < 8; ++i) tot += red[i];
    const float mean = tot * (1.0f / 1024.0f);
    float dx = v.x - mean, dy = v.y - mean, dz = v.z - mean, dw = v.w - mean;
    float q = dx * dx + dy * dy + dz * dz + dw * dw;
#pragma unroll
    for (int m = 16; m >= 1; m >>= 1) q += __shfl_xor_sync(~0u, q, m);
    __syncthreads();
    if (lane == 0) red[w] = q;
    __syncthreads();
    float qt = 0.f;
#pragma unroll
    for (int i = 0; i < 8; ++i) qt += red[i];
    const float rstd = rsqrtf(qt * (1.0f / 1024.0f) + 1e-5f);
    const int j = tid * 4;
    float4 g4 = *(const float4*)&g1[j];
    float4 b4 = *(const float4*)&be1[j];
    __align__(8) fp16 hb[4];
    hb[0] = __float2half_rn(gelu_(dx * rstd * g4.x + b4.x));
    hb[1] = __float2half_rn(gelu_(dy * rstd * g4.y + b4.y));
    hb[2] = __float2half_rn(gelu_(dz * rstd * g4.z + b4.z));
    hb[3] = __float2half_rn(gelu_(dw * rstd * g4.w + b4.w));
    *(uint2*)(g_uHi + row * 1024 + j) = *(uint2*)hb;
}

__global__ void k_setx(const float* __restrict__ st) {
    int i = blockIdx.x * blockDim.x + threadIdx.x;
    if (i < NR) g_x[i] = st[0];
}

// -------- weight prep --------
__global__ void k_cvtWhh(const float* __restrict__ W_hh) {
    int i = blockIdx.x * blockDim.x + threadIdx.x;
    if (i >= 1536 * 512) return;
    g_WhhHi[i] = __float2half_rn(W_hh[i]);
}
__global__ void k_splitWoT(const float* __restrict__ Wo1) {
    int i = blockIdx.x * blockDim.x + threadIdx.x;
    if (i >= 512 * 256) return;
    int k = i >> 8, n = i & 255;
    g_Wo1Hi[n * 512 + k] = __float2half_rn(Wo1[i]);
}
__global__ void k_splitW2T(const float* __restrict__ W2) {
    int i = blockIdx.x * blockDim.x + threadIdx.x;
    if (i >= 1024 * 512) return;
    int k = i >> 9, n = i & 511;
    float x = W2[i];
    fp16 h = __float2half_rn(x);
    g_W2Hi[n * 1024 + k] = h;
    g_W2Lo[n * 1024 + k] = __float2half_rn(x - __half2float(h));
}
__global__ void k_splitW1T(const float* __restrict__ W1) {
    int i = blockIdx.x * blockDim.x + threadIdx.x;
    if (i >= 1024 * 192) return;
    int n = i / 192, k = i % 192;
    float x = (k < 160) ? W1[(size_t)k * 1024 + n] : 0.f;
    fp16 h = __float2half_rn(x);
    g_W1Hi[i] = h;
    g_W1Lo[i] = __float2half_rn(x - __half2float(h));
}

// ============== GRU step: weight-resident persistent tiles ==================
// Grid (8 bJ, 64). Block loads full B tile (3g x 64j x 512K = 196KB) ONCE,
// loops over 8 bM tiles with double-buffered A. SMEM = 224KB.
// A bufs @ 0 / 16384 (16KB each); B chunk ck @ 32768 + ck*24576.
#define GRU_SMEM 229376

__device__ __forceinline__ void gru_copyA(uint32_t sb, int m_abs, int c,
                                          int tid, const fp16* hiIn) {
#pragma unroll
    for (int i = 0; i < 2; ++i) {
        int seg = tid + 512 * i, row = seg >> 3, s = seg & 7;
        const fp16* src = hiIn + (size_t)(m_abs * 128 + row) * 512 + c * 64 + s * 8;
        cpasync16(sb + (c & 1) * 16384 + swz(row * 128 + s * 16), src);
    }
}

__global__ __launch_bounds__(512, 1) void k_gru_mma(
    const float* __restrict__ W_ih, const float* __restrict__ b_ih,
    const float* __restrict__ b_hh, int t)
{
    extern __shared__ char smem[];
    const fp16* hiIn  = (t & 1) ? g_hiB : g_hiA;
    const fp16* loIn  = (t & 1) ? g_loB : g_loA;
    fp16*       hiOut = (t & 1) ? g_hiA : g_hiB;
    fp16*       loOut = (t & 1) ? g_loA : g_loB;

    const int bJ = blockIdx.x, gY = blockIdx.y, tid = threadIdx.x;
    const int wid = tid >> 5, lane = tid & 31;
    const int mgrp = wid >> 2, ngrp = wid & 3;
    uint32_t sb = smem_u32(smem);

    // ---- load full B tile once (8 chunk-subtiles of 24576B) ----
#pragma unroll
    for (int i = 0; i < 24; ++i) {
        int ck = i / 3;
        int seg = (i % 3) * 512 + tid;           // 0..1535 within chunk
        int row = seg >> 3, s = seg & 7;
        int grow = (row >> 6) * 512 + bJ * 64 + (row & 63);
        const fp16* src = g_WhhHi + (size_t)grow * 512 + ck * 64 + s * 8;
        cpasync16(sb + 32768 + ck * 24576 + swz(row * 128 + s * 16), src);
    }
    gru_copyA(sb, gY * 8, 0, tid, hiIn);
    CP_COMMIT();

    for (int m = 0; m < 8; ++m) {
        const int bM = gY * 8 + m;
        float acc[3][2][2][4];
#pragma unroll
        for (int g = 0; g < 3; ++g)
#pragma unroll
            for (int mt = 0; mt < 2; ++mt)
#pragma unroll
                for (int nt = 0; nt < 2; ++nt)
#pragma unroll
                    for (int c = 0; c < 4; ++c) acc[g][mt][nt][c] = 0.f;

        for (int c = 0; c < 8; ++c) {
            if (c + 1 < 8) { gru_copyA(sb, bM, c + 1, tid, hiIn); CP_COMMIT(); CP_WAIT1(); }
            else if (m + 1 < 8) { gru_copyA(sb, bM + 1, 0, tid, hiIn); CP_COMMIT(); CP_WAIT1(); }
            else CP_WAIT0();
            __syncthreads();
#pragma unroll
            for (int ks = 0; ks < 4; ++ks) {
                uint32_t aH[2][4], bH[3][4];
#pragma unroll
                for (int mt = 0; mt < 2; ++mt) {
                    int arow = mgrp * 32 + mt * 16 + (lane & 15);
                    uint32_t off = swz(arow * 128 + ks * 32 + (lane >> 4) * 16);
                    ldmx4(aH[mt], sb + (c & 1) * 16384 + off);
                }
#pragma unroll
                for (int g = 0; g < 3; ++g) {
                    int brow = g * 64 + ngrp * 16 + (lane & 7) + ((lane >> 4) & 1) * 8;
                    uint32_t boff = swz(brow * 128 + ks * 32 + ((lane >> 3) & 1) * 16);
                    ldmx4(bH[g], sb + 32768 + c * 24576 + boff);
                }
#pragma unroll
                for (int g = 0; g < 3; ++g)
#pragma unroll
                    for (int mt = 0; mt < 2; ++mt)
#pragma unroll
                        for (int nt = 0; nt < 2; ++nt)
                            mma_fp16(acc[g][mt][nt], aH[mt], bH[g] + nt * 2);
            }
            __syncthreads();
        }

        // ---- gate epilogue (overlaps the A(m+1,0) cp.async in flight) ----
#pragma unroll
        for (int nt = 0; nt < 2; ++nt) {
            const int j = bJ * 64 + ngrp * 16 + nt * 8 + (lane & 3) * 2;
            float wih[3][2], bih[3][2], bhh[3][2];
#pragma unroll
            for (int g = 0; g < 3; ++g)
#pragma unroll
                for (int cc = 0; cc < 2; ++cc) {
                    wih[g][cc] = W_ih[g * 512 + j + cc];
                    bih[g][cc] = b_ih[g * 512 + j + cc];
                    bhh[g][cc] = b_hh[g * 512 + j + cc];
                }
#pragma unroll
            for (int mt = 0; mt < 2; ++mt)
#pragma unroll
                for (int half = 0; half < 2; ++half) {
                    int row = bM * 128 + mgrp * 32 + mt * 16 + (lane >> 2) + half * 8;
                    float xi = g_x[row];
                    __half2 h2 = *(const __half2*)(hiIn + (size_t)row * 512 + j);
                    __half2 l2 = *(const __half2*)(loIn + (size_t)row * 512 + j);
                    float hOld[2] = { __half2float(h2.x) + __half2float(l2.x),
                                      __half2float(h2.y) + __half2float(l2.y) };
                    float hn[2];
#pragma unroll
                    for (int cc = 0; cc < 2; ++cc) {
                        float ghr = acc[0][mt][nt][half * 2 + cc];
                        float ghz = acc[1][mt][nt][half * 2 + cc];
                        float ghn = acc[2][mt][nt][half * 2 + cc];
                        float rr = sig_(fmaf(xi, wih[0][cc], bih[0][cc]) + ghr + bhh[0][cc]);
                        float zz = sig_(fmaf(xi, wih[1][cc], bih[1][cc]) + ghz + bhh[1][cc]);
                        float nn = tanhf(fmaf(xi, wih[2][cc], bih[2][cc]) + rr * (ghn + bhh[2][cc]));
                        hn[cc] = (1.0f - zz) * nn + zz * hOld[cc];
                    }
                    fp16 h0 = __float2half_rn(hn[0]), h1 = __float2half_rn(hn[1]);
                    __half2 hh; hh.x = h0; hh.y = h1;
                    __half2 ll;
                    ll.x = __float2half_rn(hn[0] - __half2float(h0));
                    ll.y = __float2half_rn(hn[1] - __half2float(h1));
                    *(__half2*)(hiOut + (size_t)row * 512 + j) = hh;
                    *(__half2*)(loOut + (size_t)row * 512 + j) = ll;
                }
        }
    }
}

// ====== fused output head: 64-row blocks, register-resident LN =============
// 256 threads (8 warps = 2 mgrp x 4 ngrp), warp = 32 rows x 64 cols.
// SMEM: A 2x8KB @0/8192, B 2x32KB @16384/49152, red[64][4] @81920,
//       mean[64] @82944, rstd[64] @83200. Total 83456 -> 2 CTAs/SM.
#define OH_SMEM 83456

__device__ __forceinline__ void oh_copy(uint32_t sb, int c, int b, int bM,
                                        int tid, const fp16* hiIn) {
#pragma unroll
    for (int i = 0; i < 2; ++i) {            // A: 512 segs (64 rows)
        int seg = tid + 256 * i, row = seg >> 3, s = seg & 7;
        const fp16* src = hiIn + (size_t)(bM * 64 + row) * 512 + c * 64 + s * 8;
        cpasync16(sb + b * 8192 + swz(row * 128 + s * 16), src);
    }
#pragma unroll
    for (int i = 0; i < 8; ++i) {            // B: 2048 segs (256 rows)
        int seg = tid + 256 * i, row = seg >> 3, s = seg & 7;
        const fp16* src = g_Wo1Hi + (size_t)row * 512 + c * 64 + s * 8;
        cpasync16(sb + 16384 + b * 32768 + swz(row * 128 + s * 16), src);
    }
}

__global__ __launch_bounds__(256, 2) void k_outhead(
    const float* __restrict__ bo1, const float* __restrict__ go,
    const float* __restrict__ beo, const float* __restrict__ Wo2,
    const float* __restrict__ bo2, float* __restrict__ out, int t)
{
    extern __shared__ char smem[];
    const fp16* hiIn = (t & 1) ? g_hiA : g_hiB;   // h_new from gru(t)
    const int bM = blockIdx.x, tid = threadIdx.x;
    const int wid = tid >> 5, lane = tid & 31;
    const int mgrp = wid >> 2, ngrp = wid & 3;
    uint32_t sb = smem_u32(smem);

    float acc[2][8][4];
#pragma unroll
    for (int mt = 0; mt < 2; ++mt)
#pragma unroll
        for (int n8 = 0; n8 < 8; ++n8)
#pragma unroll
            for (int c = 0; c < 4; ++c) acc[mt][n8][c] = 0.f;

    oh_copy(sb, 0, 0, bM, tid, hiIn);
    CP_COMMIT();

    for (int c = 0; c < 8; ++c) {
        int b = c & 1;
        if (c + 1 < 8) { oh_copy(sb, c + 1, b ^ 1, bM, tid, hiIn); CP_COMMIT(); CP_WAIT1(); }
        else CP_WAIT0();
        __syncthreads();
#pragma unroll
        for (int ks = 0; ks < 4; ++ks) {
            uint32_t aH[2][4];
#pragma unroll
            for (int mt = 0; mt < 2; ++mt) {
                int arow = mgrp * 32 + mt * 16 + (lane & 15);
                uint32_t off = swz(arow * 128 + ks * 32 + (lane >> 4) * 16);
                ldmx4(aH[mt], sb + b * 8192 + off);
            }
#pragma unroll
            for (int g16 = 0; g16 < 4; ++g16) {
                int brow = ngrp * 64 + g16 * 16 + (lane & 7) + ((lane >> 4) & 1) * 8;
                uint32_t boff = swz(brow * 128 + ks * 32 + ((lane >> 3) & 1) * 16);
                uint32_t bB[4];
                ldmx4(bB, sb + 16384 + b * 32768 + boff);
#pragma unroll
                for (int mt = 0; mt < 2; ++mt)
#pragma unroll
                    for (int nt = 0; nt < 2; ++nt)
                        mma_fp16(acc[mt][g16 * 2 + nt], aH[mt], bB + nt * 2);
            }
        }
        __syncthreads();
    }

    // ---- register-resident LN + GELU + dot via partial reductions ----
    float* red   = (float*)(smem + 81920);    // [64][4]
    float* meanv = (float*)(smem + 82944);    // [64]
    float* rstdv = (float*)(smem + 83200);    // [64]

    float bo1v[8][2];
#pragma unroll
    for (int n8 = 0; n8 < 8; ++n8)
#pragma unroll
        for (int cc = 0; cc < 2; ++cc)
            bo1v[n8][cc] = bo1[ngrp * 64 + n8 * 8 + (lane & 3) * 2 + cc];

    // pass 1: row sums
#pragma unroll
    for (int mt = 0; mt < 2; ++mt)
#pragma unroll
        for (int half = 0; half < 2; ++half) {
            int row_l = mgrp * 32 + mt * 16 + (lane >> 2) + half * 8;
            float s = 0.f;
#pragma unroll
            for (int n8 = 0; n8 < 8; ++n8)
#pragma unroll
                for (int cc = 0; cc < 2; ++cc)
                    s += acc[mt][n8][half * 2 + cc] + bo1v[n8][cc];
            s += __shfl_xor_sync(~0u, s, 1);
            s += __shfl_xor_sync(~0u, s, 2);
            if ((lane & 3) == 0) red[row_l * 4 + ngrp] = s;
        }
    __syncthreads();
    if (tid < 64)
        meanv[tid] = (red[tid * 4] + red[tid * 4 + 1] + red[tid * 4 + 2] + red[tid * 4 + 3])
                     * (1.0f / 256.0f);
    __syncthreads();

    // pass 2: variance
#pragma unroll
    for (int mt = 0; mt < 2; ++mt)
#pragma unroll
        for (int half = 0; half < 2; ++half) {
            int row_l = mgrp * 32 + mt * 16 + (lane >> 2) + half * 8;
            float mu = meanv[row_l];
            float q = 0.f;
#pragma unroll
            for (int n8 = 0; n8 < 8; ++n8)
#pragma unroll
                for (int cc = 0; cc < 2; ++cc) {
                    float d = acc[mt][n8][half * 2 + cc] + bo1v[n8][cc] - mu;
                    q += d * d;
                }
            q += __shfl_xor_sync(~0u, q, 1);
            q += __shfl_xor_sync(~0u, q, 2);
            if ((lane & 3) == 0) red[row_l * 4 + ngrp] = q;
        }
    __syncthreads();
    if (tid < 64)
        rstdv[tid] = rsqrtf((red[tid * 4] + red[tid * 4 + 1] + red[tid * 4 + 2] + red[tid * 4 + 3])
                            * (1.0f / 256.0f) + 1e-5f);
    __syncthreads();

    // pass 3: y partials
    {
        float mu[2][2], rs[2][2];
#pragma unroll
        for (int mt = 0; mt < 2; ++mt)
#pragma unroll
            for (int half = 0; half < 2; ++half) {
                int row_l = mgrp * 32 + mt * 16 + (lane >> 2) + half * 8;
                mu[mt][half] = meanv[row_l];
                rs[mt][half] = rstdv[row_l];
            }
        float yp[2][2] = {{0.f, 0.f}, {0.f, 0.f}};
#pragma unroll
        for (int n8 = 0; n8 < 8; ++n8) {
#pragma unroll
            for (int cc = 0; cc < 2; ++cc) {
                int col = ngrp * 64 + n8 * 8 + (lane & 3) * 2 + cc;
                float gv = go[col], bv = beo[col], wv = Wo2[col];
#pragma unroll
                for (int mt = 0; mt < 2; ++mt)
#pragma unroll
                    for (int half = 0; half < 2; ++half) {
                        float v = acc[mt][n8][half * 2 + cc] + bo1v[n8][cc];
                        float ln = (v - mu[mt][half]) * rs[mt][half] * gv + bv;
                        yp[mt][half] += gelu_(ln) * wv;
                    }
            }
        }
        __syncthreads();   // red reuse
#pragma unroll
        for (int mt = 0; mt < 2; ++mt)
#pragma unroll
            for (int half = 0; half < 2; ++half) {
                int row_l = mgrp * 32 + mt * 16 + (lane >> 2) + half * 8;
                float y = yp[mt][half];
                y += __shfl_xor_sync(~0u, y, 1);
                y += __shfl_xor_sync(~0u, y, 2);
                if ((lane & 3) == 0) red[row_l * 4 + ngrp] = y;
            }
    }
    __syncthreads();
    if (tid < 64) {
        float yy = red[tid * 4] + red[tid * 4 + 1] + red[tid * 4 + 2] + red[tid * 4 + 3] + bo2[0];
        int row = bM * 64 + tid;
        out[(size_t)row * 20 + t] = yy;
        g_x[row] = yy;
    }
}

// ======== generic 128-row x 64-col fp16 2-term mma GEMM (init only) =========
#define MMA64_SMEM (64 * 1024)

__device__ __forceinline__ void mma64_copy(uint32_t sb, int c, int b, int bM, int bJ,
                                           int tid, const fp16* aHi,
                                           const fp16* bHi, const fp16* bLo, int K) {
#pragma unroll
    for (int i = 0; i < 4; ++i) {
        int seg = tid + 256 * i, row = seg >> 3, s = seg & 7;
        const fp16* src = aHi + (size_t)(bM * 128 + row) * K + c * 64 + s * 8;
        cpasync16(sb + b * 16384 + swz(row * 128 + s * 16), src);
    }
#pragma unroll
    for (int i = 0; i < 4; ++i) {
        int seg = tid + 256 * i, hl = seg >> 9, rem = seg & 511, row = rem >> 3, s = rem & 7;
        const fp16* src = (hl ? bLo : bHi) + (size_t)(bJ * 64 + row) * K + c * 64 + s * 8;
        cpasync16(sb + 32768 + b * 16384 + hl * 8192 + swz(row * 128 + s * 16), src);
    }
}

template <int KDIM, int MODE>   // MODE 1: tanh(acc+bias)->g_hiA/g_loA; MODE 2: acc+bias->g_u
__global__ __launch_bounds__(256, 2) void k_mma64(
    const fp16* __restrict__ aHi,
    const fp16* __restrict__ bHi, const fp16* __restrict__ bLo,
    const float* __restrict__ bias)
{
    extern __shared__ char smem[];
    const int bJ = blockIdx.x, bM = blockIdx.y, tid = threadIdx.x;
    const int wid = tid >> 5, lane = tid & 31;
    const int mgrp = wid >> 2, ngrp = wid & 3;
    uint32_t sb = smem_u32(smem);
    const int NCH = KDIM / 64;

    float acc[4][2][4];
#pragma unroll
    for (int mt = 0; mt < 4; ++mt)
#pragma unroll
        for (int nt = 0; nt < 2; ++nt)
#pragma unroll
            for (int c = 0; c < 4; ++c) acc[mt][nt][c] = 0.f;

    mma64_copy(sb, 0, 0, bM, bJ, tid, aHi, bHi, bLo, KDIM);
    CP_COMMIT();

    for (int c = 0; c < NCH; ++c) {
        int b = c & 1;
        if (c + 1 < NCH) { mma64_copy(sb, c + 1, b ^ 1, bM, bJ, tid, aHi, bHi, bLo, KDIM);
                           CP_COMMIT(); CP_WAIT1(); }
        else CP_WAIT0();
        __syncthreads();
#pragma unroll
        for (int ks = 0; ks < 4; ++ks) {
            uint32_t aH[4][4], bH[4], bL[4];
#pragma unroll
            for (int mt = 0; mt < 4; ++mt) {
                int arow = mgrp * 64 + mt * 16 + (lane & 15);
                uint32_t off = swz(arow * 128 + ks * 32 + (lane >> 4) * 16);
                ldmx4(aH[mt], sb + b * 16384 + off);
            }
            int brow = ngrp * 16 + (lane & 7) + ((lane >> 4) & 1) * 8;
            uint32_t boff = swz(brow * 128 + ks * 32 + ((lane >> 3) & 1) * 16);
            ldmx4(bH, sb + 32768 + b * 16384 + boff);
            ldmx4(bL, sb + 32768 + b * 16384 + 8192 + boff);
#pragma unroll
            for (int mt = 0; mt < 4; ++mt)
#pragma unroll
                for (int nt = 0; nt < 2; ++nt)
                    mma_fp16(acc[mt][nt], aH[mt], bH + nt * 2);
#pragma unroll
            for (int mt = 0; mt < 4; ++mt)
#pragma unroll
                for (int nt = 0; nt < 2; ++nt)
                    mma_fp16(acc[mt][nt], aH[mt], bL + nt * 2);
        }
        __syncthreads();
    }

#pragma unroll
    for (int nt = 0; nt < 2; ++nt) {
        const int n = bJ * 64 + ngrp * 16 + nt * 8 + (lane & 3) * 2;
#pragma unroll
        for (int mt = 0; mt < 4; ++mt)
#pragma unroll
            for (int half = 0; half < 2; ++half) {
                int row = bM * 128 + mgrp * 64 + mt * 16 + (lane >> 2) + half * 8;
                if (MODE == 1) {
                    float hn0 = tanhf(acc[mt][nt][half * 2]     + bias[n]);
                    float hn1 = tanhf(acc[mt][nt][half * 2 + 1] + bias[n + 1]);
                    fp16 h0 = __float2half_rn(hn0), h1 = __float2half_rn(hn1);
                    __half2 hh; hh.x = h0; hh.y = h1;
                    __half2 ll;
                    ll.x = __float2half_rn(hn0 - __half2float(h0));
                    ll.y = __float2half_rn(hn1 - __half2float(h1));
                    *(__half2*)(g_hiA + (size_t)row * 512 + n) = hh;
                    *(__half2*)(g_loA + (size_t)row * 512 + n) = ll;
                } else {
                    *(float2*)(g_u + (size_t)row * 1024 + n) =
                        make_float2(acc[mt][nt][half * 2] + bias[n],
                                    acc[mt][nt][half * 2 + 1] + bias[n + 1]);
                }
            }
    }
}

// ================================== host ====================================
extern "C" void kernel_launch(void* const* d_in, const int* in_sizes, int n_in,
                              void* d_out, int out_size) {
    const float* z_q   = (const float*)d_in[0];
    const float* f_pr  = (const float*)d_in[1];
    const float* W1    = (const float*)d_in[2];
    const float* b1    = (const float*)d_in[3];
    const float* g1    = (const float*)d_in[4];
    const float* be1   = (const float*)d_in[5];
    const float* W2    = (const float*)d_in[6];
    const float* b2    = (const float*)d_in[7];
    const float* start = (const float*)d_in[8];
    const float* W_ih  = (const float*)d_in[9];
    const float* W_hh  = (const float*)d_in[10];
    const float* b_ih  = (const float*)d_in[11];
    const float* b_hh  = (const float*)d_in[12];
    const float* Wo1   = (const float*)d_in[13];
    const float* bo1   = (const float*)d_in[14];
    const float* go    = (const float*)d_in[15];
    const float* beo   = (const float*)d_in[16];
    const float* Wo2   = (const float*)d_in[17];
    const float* bo2   = (const float*)d_in[18];
    float* out = (float*)d_out;

    cudaFuncSetAttribute(k_gru_mma, cudaFuncAttributeMaxDynamicSharedMemorySize, GRU_SMEM);
    cudaFuncSetAttribute(k_outhead, cudaFuncAttributeMaxDynamicSharedMemorySize, OH_SMEM);
    cudaFuncSetAttribute(k_mma64<1024, 1>, cudaFuncAttributeMaxDynamicSharedMemorySize, MMA64_SMEM);
    cudaFuncSetAttribute(k_mma64<192, 2>, cudaFuncAttributeMaxDynamicSharedMemorySize, MMA64_SMEM);

    fp16 *cHiP, *uHiP, *w2HiP, *w2LoP, *w1HiP, *w1LoP;
    cudaGetSymbolAddress((void**)&cHiP, g_cHi);
    cudaGetSymbolAddress((void**)&uHiP, g_uHi);
    cudaGetSymbolAddress((void**)&w2HiP, g_W2Hi);
    cudaGetSymbolAddress((void**)&w2LoP, g_W2Lo);
    cudaGetSymbolAddress((void**)&w1HiP, g_W1Hi);
    cudaGetSymbolAddress((void**)&w1LoP, g_W1Lo);

    // weight prep
    k_cvtWhh<<<(1536 * 512 + 255) / 256, 256>>>(W_hh);
    k_splitWoT<<<(512 * 256 + 255) / 256, 256>>>(Wo1);
    k_splitW2T<<<(1024 * 512 + 255) / 256, 256>>>(W2);
    k_splitW1T<<<(1024 * 192 + 255) / 256, 256>>>(W1);

    // init MLP
    k_prep<<<(int)(((size_t)NR * 192 + 255) / 256), 256>>>(z_q, f_pr);
    k_mma64<192, 2><<<dim3(16, NR / 128), 256, MMA64_SMEM>>>(cHiP, w1HiP, w1LoP, b1);
    k_lngelu<<<NR, 256>>>(g1, be1);
    k_mma64<1024, 1><<<dim3(8, NR / 128), 256, MMA64_SMEM>>>(uHiP, w2HiP, w2LoP, b2);
    k_setx<<<NR / 256, 256>>>(start);

    // recurrence
    for (int t = 0; t < 20; ++t) {
        k_gru_mma<<<dim3(8, 64), 512, GRU_SMEM>>>(W_ih, b_ih, b_hh, t);
        k_outhead<<<NR / 64, 256, OH_SMEM>>>(bo1, go, beo, Wo2, bo2, out, t);
    }
}

// round 15
// speedup vs baseline: 1.0600x; 1.0600x over previous
#include <cuda_runtime.h>
#include <cuda_fp16.h>
#include <cstdint>

#define NR 65536
typedef __half fp16;

// ----------------------------- device scratch ------------------------------
__device__ float g_u[(size_t)NR * 1024];
__device__ fp16  g_cHi[(size_t)NR * 192];    // concat(z,f) padded to K=192
__device__ fp16  g_uHi[(size_t)NR * 1024];
__device__ fp16  g_hiA[(size_t)NR * 512];
__device__ fp16  g_loA[(size_t)NR * 512];
__device__ fp16  g_hiB[(size_t)NR * 512];
__device__ fp16  g_loB[(size_t)NR * 512];
__device__ float g_x[NR];
__device__ fp16  g_WhhHi[1536 * 512];
__device__ fp16  g_Wo1Hi[256 * 512];     // transposed [N=256, K=512], hi only
__device__ fp16  g_W2Hi[512 * 1024];     // transposed [N=512, K=1024]
__device__ fp16  g_W2Lo[512 * 1024];
__device__ fp16  g_W1Hi[1024 * 192];     // transposed+padded [N=1024, K=192]
__device__ fp16  g_W1Lo[1024 * 192];

// ----------------------------- small helpers -------------------------------
__device__ __forceinline__ float sig_(float x) { return 1.0f / (1.0f + expf(-x)); }
__device__ __forceinline__ float gelu_(float x) {
    return 0.5f * x * (1.0f + erff(x * 0.70710678f));
}
__device__ __forceinline__ uint32_t smem_u32(const void* p) {
    uint32_t a;
    asm("{ .reg .u64 t; cvta.to.shared.u64 t, %1; cvt.u32.u64 %0, t; }" : "=r"(a) : "l"(p));
    return a;
}
__device__ __forceinline__ uint32_t swz(uint32_t off) { return off ^ ((off >> 3) & 0x70); }

__device__ __forceinline__ void cpasync16(uint32_t saddr, const void* gptr) {
    asm volatile("{ .reg .u64 g; cvta.to.global.u64 g, %1; "
                 "cp.async.cg.shared.global [%0], [g], 16; }"
                 :: "r"(saddr), "l"(gptr) : "memory");
}
#define CP_COMMIT() asm volatile("cp.async.commit_group;" ::: "memory")
#define CP_WAIT1()  asm volatile("cp.async.wait_group 1;" ::: "memory")
#define CP_WAIT0()  asm volatile("cp.async.wait_group 0;" ::: "memory")

__device__ __forceinline__ void ldmx4(uint32_t* r, uint32_t addr) {
    asm volatile("ldmatrix.sync.aligned.m8n8.x4.shared.b16 {%0,%1,%2,%3}, [%4];"
        : "=r"(r[0]), "=r"(r[1]), "=r"(r[2]), "=r"(r[3]) : "r"(addr));
}
__device__ __forceinline__ void mma_fp16(float* d, const uint32_t* a, const uint32_t* b) {
    asm volatile("mma.sync.aligned.m16n8k16.row.col.f32.f16.f16.f32 "
        "{%0,%1,%2,%3}, {%4,%5,%6,%7}, {%8,%9}, {%0,%1,%2,%3};"
        : "+f"(d[0]), "+f"(d[1]), "+f"(d[2]), "+f"(d[3])
        : "r"(a[0]), "r"(a[1]), "r"(a[2]), "r"(a[3]), "r"(b[0]), "r"(b[1]));
}

// =========================== init-path kernels =============================
__global__ void k_prep(const float* __restrict__ z, const float* __restrict__ f) {
    size_t i = (size_t)blockIdx.x * blockDim.x + threadIdx.x;
    if (i >= (size_t)NR * 192) return;
    int row = (int)(i / 192), col = (int)(i % 192);
    float x = (col < 128) ? z[(size_t)row * 128 + col]
            : (col < 160) ? f[(size_t)row * 32 + col - 128] : 0.f;
    g_cHi[i] = __float2half_rn(x);
}

__global__ __launch_bounds__(256) void k_lngelu(
    const float* __restrict__ g1, const float* __restrict__ be1)
{
    const size_t row = blockIdx.x;
    const int tid = threadIdx.x, lane = tid & 31, w = tid >> 5;
    const float* up = g_u + row * 1024 + tid * 4;
    float4 v = *(const float4*)up;
    __shared__ float red[8];
    float s = v.x + v.y + v.z + v.w;
#pragma unroll
    for (int m = 16; m >= 1; m >>= 1) s += __shfl_xor_sync(~0u, s, m);
    if (lane == 0) red[w] = s;
    __syncthreads();
    float tot = 0.f;
#pragma unroll
    for (int i = 0; i < 8; ++i) tot += red[i];
    const float mean = tot * (1.0f / 1024.0f);
    float dx = v.x - mean, dy = v.y - mean, dz = v.z - mean, dw = v.w - mean;
    float q = dx * dx + dy * dy + dz * dz + dw * dw;
#pragma unroll
    for (int m = 16; m >= 1; m >>= 1) q += __shfl_xor_sync(~0u, q, m);
    __syncthreads();
    if (lane == 0) red[w] = q;
    __syncthreads();
    float qt = 0.f;
#pragma unroll
    for (int i = 0; i < 8; ++i) qt += red[i];
    const float rstd = rsqrtf(qt * (1.0f / 1024.0f) + 1e-5f);
    const int j = tid * 4;
    float4 g4 = *(const float4*)&g1[j];
    float4 b4 = *(const float4*)&be1[j];
    __align__(8) fp16 hb[4];
    hb[0] = __float2half_rn(gelu_(dx * rstd * g4.x + b4.x));
    hb[1] = __float2half_rn(gelu_(dy * rstd * g4.y + b4.y));
    hb[2] = __float2half_rn(gelu_(dz * rstd * g4.z + b4.z));
    hb[3] = __float2half_rn(gelu_(dw * rstd * g4.w + b4.w));
    *(uint2*)(g_uHi + row * 1024 + j) = *(uint2*)hb;
}

__global__ void k_setx(const float* __restrict__ st) {
    int i = blockIdx.x * blockDim.x + threadIdx.x;
    if (i < NR) g_x[i] = st[0];
}

// -------- weight prep --------
__global__ void k_cvtWhh(const float* __restrict__ W_hh) {
    int i = blockIdx.x * blockDim.x + threadIdx.x;
    if (i >= 1536 * 512) return;
    g_WhhHi[i] = __float2half_rn(W_hh[i]);
}
__global__ void k_splitWoT(const float* __restrict__ Wo1) {
    int i = blockIdx.x * blockDim.x + threadIdx.x;
    if (i >= 512 * 256) return;
    int k = i >> 8, n = i & 255;
    g_Wo1Hi[n * 512 + k] = __float2half_rn(Wo1[i]);
}
__global__ void k_splitW2T(const float* __restrict__ W2) {
    int i = blockIdx.x * blockDim.x + threadIdx.x;
    if (i >= 1024 * 512) return;
    int k = i >> 9, n = i & 511;
    float x = W2[i];
    fp16 h = __float2half_rn(x);
    g_W2Hi[n * 1024 + k] = h;
    g_W2Lo[n * 1024 + k] = __float2half_rn(x - __half2float(h));
}
__global__ void k_splitW1T(const float* __restrict__ W1) {
    int i = blockIdx.x * blockDim.x + threadIdx.x;
    if (i >= 1024 * 192) return;
    int n = i / 192, k = i % 192;
    float x = (k < 160) ? W1[(size_t)k * 1024 + n] : 0.f;
    fp16 h = __float2half_rn(x);
    g_W1Hi[i] = h;
    g_W1Lo[i] = __float2half_rn(x - __half2float(h));
}

// ============================ GRU step (mma.sync) ===========================
// R13-proven version (byte-identical): 1-term fp16, SW128, K-chunk 64,
// double-buffered cp.async, 80KB smem, 512 threads, grid (8, 512).
#define GRU_SMEM (80 * 1024)

__device__ __forceinline__ void gru_copy(uint32_t sb, int c, int b, int bM, int bJ,
                                         int tid, const fp16* hiIn) {
#pragma unroll
    for (int i = 0; i < 2; ++i) {            // A: 1024 segs of 16B
        int seg = tid + 512 * i, row = seg >> 3, s = seg & 7;
        const fp16* src = hiIn + (size_t)(bM * 128 + row) * 512 + c * 64 + s * 8;
        cpasync16(sb + b * 16384 + swz(row * 128 + s * 16), src);
    }
#pragma unroll
    for (int i = 0; i < 3; ++i) {            // B: 1536 segs of 16B (192 rows)
        int seg = tid + 512 * i, row = seg >> 3, s = seg & 7;
        int grow = (row >> 6) * 512 + bJ * 64 + (row & 63);
        const fp16* src = g_WhhHi + (size_t)grow * 512 + c * 64 + s * 8;
        cpasync16(sb + 32768 + b * 24576 + swz(row * 128 + s * 16), src);
    }
}

__global__ __launch_bounds__(512, 1) void k_gru_mma(
    const float* __restrict__ W_ih, const float* __restrict__ b_ih,
    const float* __restrict__ b_hh, int t)
{
    extern __shared__ char smem[];
    const fp16* hiIn  = (t & 1) ? g_hiB : g_hiA;
    const fp16* loIn  = (t & 1) ? g_loB : g_loA;
    fp16*       hiOut = (t & 1) ? g_hiA : g_hiB;
    fp16*       loOut = (t & 1) ? g_loA : g_loB;

    const int bJ = blockIdx.x, bM = blockIdx.y, tid = threadIdx.x;
    const int wid = tid >> 5, lane = tid & 31;
    const int mgrp = wid >> 2, ngrp = wid & 3;
    uint32_t sb = smem_u32(smem);

    float acc[3][2][2][4];
#pragma unroll
    for (int g = 0; g < 3; ++g)
#pragma unroll
        for (int mt = 0; mt < 2; ++mt)
#pragma unroll
            for (int nt = 0; nt < 2; ++nt)
#pragma unroll
                for (int c = 0; c < 4; ++c) acc[g][mt][nt][c] = 0.f;

    gru_copy(sb, 0, 0, bM, bJ, tid, hiIn);
    CP_COMMIT();

    for (int c = 0; c < 8; ++c) {
        int b = c & 1;
        if (c + 1 < 8) { gru_copy(sb, c + 1, b ^ 1, bM, bJ, tid, hiIn); CP_COMMIT(); CP_WAIT1(); }
        else CP_WAIT0();
        __syncthreads();
#pragma unroll
        for (int ks = 0; ks < 4; ++ks) {
            uint32_t aH[2][4], bH[3][4];
#pragma unroll
            for (int mt = 0; mt < 2; ++mt) {
                int arow = mgrp * 32 + mt * 16 + (lane & 15);
                uint32_t off = swz(arow * 128 + ks * 32 + (lane >> 4) * 16);
                ldmx4(aH[mt], sb + b * 16384 + off);
            }
#pragma unroll
            for (int g = 0; g < 3; ++g) {
                int brow = g * 64 + ngrp * 16 + (lane & 7) + ((lane >> 4) & 1) * 8;
                uint32_t boff = swz(brow * 128 + ks * 32 + ((lane >> 3) & 1) * 16);
                ldmx4(bH[g], sb + 32768 + b * 24576 + boff);
            }
#pragma unroll
            for (int g = 0; g < 3; ++g)
#pragma unroll
                for (int mt = 0; mt < 2; ++mt)
#pragma unroll
                    for (int nt = 0; nt < 2; ++nt)
                        mma_fp16(acc[g][mt][nt], aH[mt], bH[g] + nt * 2);
        }
        __syncthreads();
    }

    // ---- in-register gate epilogue (h_old reconstructed from hi/lo) ----
#pragma unroll
    for (int nt = 0; nt < 2; ++nt) {
        const int j = bJ * 64 + ngrp * 16 + nt * 8 + (lane & 3) * 2;
        float wih[3][2], bih[3][2], bhh[3][2];
#pragma unroll
        for (int g = 0; g < 3; ++g)
#pragma unroll
            for (int cc = 0; cc < 2; ++cc) {
                wih[g][cc] = W_ih[g * 512 + j + cc];
                bih[g][cc] = b_ih[g * 512 + j + cc];
                bhh[g][cc] = b_hh[g * 512 + j + cc];
            }
#pragma unroll
        for (int mt = 0; mt < 2; ++mt)
#pragma unroll
            for (int half = 0; half < 2; ++half) {
                int row = bM * 128 + mgrp * 32 + mt * 16 + (lane >> 2) + half * 8;
                float xi = g_x[row];
                __half2 h2 = *(const __half2*)(hiIn + (size_t)row * 512 + j);
                __half2 l2 = *(const __half2*)(loIn + (size_t)row * 512 + j);
                float hOld[2] = { __half2float(h2.x) + __half2float(l2.x),
                                  __half2float(h2.y) + __half2float(l2.y) };
                float hn[2];
#pragma unroll
                for (int cc = 0; cc < 2; ++cc) {
                    float ghr = acc[0][mt][nt][half * 2 + cc];
                    float ghz = acc[1][mt][nt][half * 2 + cc];
                    float ghn = acc[2][mt][nt][half * 2 + cc];
                    float rr = sig_(fmaf(xi, wih[0][cc], bih[0][cc]) + ghr + bhh[0][cc]);
                    float zz = sig_(fmaf(xi, wih[1][cc], bih[1][cc]) + ghz + bhh[1][cc]);
                    float nn = tanhf(fmaf(xi, wih[2][cc], bih[2][cc]) + rr * (ghn + bhh[2][cc]));
                    hn[cc] = (1.0f - zz) * nn + zz * hOld[cc];
                }
                fp16 h0 = __float2half_rn(hn[0]), h1 = __float2half_rn(hn[1]);
                __half2 hh; hh.x = h0; hh.y = h1;
                __half2 ll;
                ll.x = __float2half_rn(hn[0] - __half2float(h0));
                ll.y = __float2half_rn(hn[1] - __half2float(h1));
                *(__half2*)(hiOut + (size_t)row * 512 + j) = hh;
                *(__half2*)(loOut + (size_t)row * 512 + j) = ll;
            }
    }
}

// ====== fused output head: 64-row blocks, register-resident LN =============
// R14 version (validated correct): 256 threads (2 mgrp x 4 ngrp), warp =
// 32 rows x 64 cols. SMEM 83456 -> 2 CTAs/SM, no fp32 transpose.
#define OH_SMEM 83456

__device__ __forceinline__ void oh_copy(uint32_t sb, int c, int b, int bM,
                                        int tid, const fp16* hiIn) {
#pragma unroll
    for (int i = 0; i < 2; ++i) {            // A: 512 segs (64 rows)
        int seg = tid + 256 * i, row = seg >> 3, s = seg & 7;
        const fp16* src = hiIn + (size_t)(bM * 64 + row) * 512 + c * 64 + s * 8;
        cpasync16(sb + b * 8192 + swz(row * 128 + s * 16), src);
    }
#pragma unroll
    for (int i = 0; i < 8; ++i) {            // B: 2048 segs (256 rows)
        int seg = tid + 256 * i, row = seg >> 3, s = seg & 7;
        const fp16* src = g_Wo1Hi + (size_t)row * 512 + c * 64 + s * 8;
        cpasync16(sb + 16384 + b * 32768 + swz(row * 128 + s * 16), src);
    }
}

__global__ __launch_bounds__(256, 2) void k_outhead(
    const float* __restrict__ bo1, const float* __restrict__ go,
    const float* __restrict__ beo, const float* __restrict__ Wo2,
    const float* __restrict__ bo2, float* __restrict__ out, int t)
{
    extern __shared__ char smem[];
    const fp16* hiIn = (t & 1) ? g_hiA : g_hiB;   // h_new from gru(t)
    const int bM = blockIdx.x, tid = threadIdx.x;
    const int wid = tid >> 5, lane = tid & 31;
    const int mgrp = wid >> 2, ngrp = wid & 3;
    uint32_t sb = smem_u32(smem);

    float acc[2][8][4];
#pragma unroll
    for (int mt = 0; mt < 2; ++mt)
#pragma unroll
        for (int n8 = 0; n8 < 8; ++n8)
#pragma unroll
            for (int c = 0; c < 4; ++c) acc[mt][n8][c] = 0.f;

    oh_copy(sb, 0, 0, bM, tid, hiIn);
    CP_COMMIT();

    for (int c = 0; c < 8; ++c) {
        int b = c & 1;
        if (c + 1 < 8) { oh_copy(sb, c + 1, b ^ 1, bM, tid, hiIn); CP_COMMIT(); CP_WAIT1(); }
        else CP_WAIT0();
        __syncthreads();
#pragma unroll
        for (int ks = 0; ks < 4; ++ks) {
            uint32_t aH[2][4];
#pragma unroll
            for (int mt = 0; mt < 2; ++mt) {
                int arow = mgrp * 32 + mt * 16 + (lane & 15);
                uint32_t off = swz(arow * 128 + ks * 32 + (lane >> 4) * 16);
                ldmx4(aH[mt], sb + b * 8192 + off);
            }
#pragma unroll
            for (int g16 = 0; g16 < 4; ++g16) {
                int brow = ngrp * 64 + g16 * 16 + (lane & 7) + ((lane >> 4) & 1) * 8;
                uint32_t boff = swz(brow * 128 + ks * 32 + ((lane >> 3) & 1) * 16);
                uint32_t bB[4];
                ldmx4(bB, sb + 16384 + b * 32768 + boff);
#pragma unroll
                for (int mt = 0; mt < 2; ++mt)
#pragma unroll
                    for (int nt = 0; nt < 2; ++nt)
                        mma_fp16(acc[mt][g16 * 2 + nt], aH[mt], bB + nt * 2);
            }
        }
        __syncthreads();
    }

    // ---- register-resident LN + GELU + dot via partial reductions ----
    float* red   = (float*)(smem + 81920);    // [64][4]
    float* meanv = (float*)(smem + 82944);    // [64]
    float* rstdv = (float*)(smem + 83200);    // [64]

    float bo1v[8][2];
#pragma unroll
    for (int n8 = 0; n8 < 8; ++n8)
#pragma unroll
        for (int cc = 0; cc < 2; ++cc)
            bo1v[n8][cc] = bo1[ngrp * 64 + n8 * 8 + (lane & 3) * 2 + cc];

    // pass 1: row sums
#pragma unroll
    for (int mt = 0; mt < 2; ++mt)
#pragma unroll
        for (int half = 0; half < 2; ++half) {
            int row_l = mgrp * 32 + mt * 16 + (lane >> 2) + half * 8;
            float s = 0.f;
#pragma unroll
            for (int n8 = 0; n8 < 8; ++n8)
#pragma unroll
                for (int cc = 0; cc < 2; ++cc)
                    s += acc[mt][n8][half * 2 + cc] + bo1v[n8][cc];
            s += __shfl_xor_sync(~0u, s, 1);
            s += __shfl_xor_sync(~0u, s, 2);
            if ((lane & 3) == 0) red[row_l * 4 + ngrp] = s;
        }
    __syncthreads();
    if (tid < 64)
        meanv[tid] = (red[tid * 4] + red[tid * 4 + 1] + red[tid * 4 + 2] + red[tid * 4 + 3])
                     * (1.0f / 256.0f);
    __syncthreads();

    // pass 2: variance
#pragma unroll
    for (int mt = 0; mt < 2; ++mt)
#pragma unroll
        for (int half = 0; half < 2; ++half) {
            int row_l = mgrp * 32 + mt * 16 + (lane >> 2) + half * 8;
            float mu = meanv[row_l];
            float q = 0.f;
#pragma unroll
            for (int n8 = 0; n8 < 8; ++n8)
#pragma unroll
                for (int cc = 0; cc < 2; ++cc) {
                    float d = acc[mt][n8][half * 2 + cc] + bo1v[n8][cc] - mu;
                    q += d * d;
                }
            q += __shfl_xor_sync(~0u, q, 1);
            q += __shfl_xor_sync(~0u, q, 2);
            if ((lane & 3) == 0) red[row_l * 4 + ngrp] = q;
        }
    __syncthreads();
    if (tid < 64)
        rstdv[tid] = rsqrtf((red[tid * 4] + red[tid * 4 + 1] + red[tid * 4 + 2] + red[tid * 4 + 3])
                            * (1.0f / 256.0f) + 1e-5f);
    __syncthreads();

    // pass 3: y partials
    {
        float mu[2][2], rs[2][2];
#pragma unroll
        for (int mt = 0; mt < 2; ++mt)
#pragma unroll
            for (int half = 0; half < 2; ++half) {
                int row_l = mgrp * 32 + mt * 16 + (lane >> 2) + half * 8;
                mu[mt][half] = meanv[row_l];
                rs[mt][half] = rstdv[row_l];
            }
        float yp[2][2] = {{0.f, 0.f}, {0.f, 0.f}};
#pragma unroll
        for (int n8 = 0; n8 < 8; ++n8) {
#pragma unroll
            for (int cc = 0; cc < 2; ++cc) {
                int col = ngrp * 64 + n8 * 8 + (lane & 3) * 2 + cc;
                float gv = go[col], bv = beo[col], wv = Wo2[col];
#pragma unroll
                for (int mt = 0; mt < 2; ++mt)
#pragma unroll
                    for (int half = 0; half < 2; ++half) {
                        float v = acc[mt][n8][half * 2 + cc] + bo1v[n8][cc];
                        float ln = (v - mu[mt][half]) * rs[mt][half] * gv + bv;
                        yp[mt][half] += gelu_(ln) * wv;
                    }
            }
        }
        __syncthreads();   // red reuse
#pragma unroll
        for (int mt = 0; mt < 2; ++mt)
#pragma unroll
            for (int half = 0; half < 2; ++half) {
                int row_l = mgrp * 32 + mt * 16 + (lane >> 2) + half * 8;
                float y = yp[mt][half];
                y += __shfl_xor_sync(~0u, y, 1);
                y += __shfl_xor_sync(~0u, y, 2);
                if ((lane & 3) == 0) red[row_l * 4 + ngrp] = y;
            }
    }
    __syncthreads();
    if (tid < 64) {
        float yy = red[tid * 4] + red[tid * 4 + 1] + red[tid * 4 + 2] + red[tid * 4 + 3] + bo2[0];
        int row = bM * 64 + tid;
        out[(size_t)row * 20 + t] = yy;
        g_x[row] = yy;
    }
}

// ======== generic 128-row x 64-col fp16 2-term mma GEMM (init only) =========
#define MMA64_SMEM (64 * 1024)

__device__ __forceinline__ void mma64_copy(uint32_t sb, int c, int b, int bM, int bJ,
                                           int tid, const fp16* aHi,
                                           const fp16* bHi, const fp16* bLo, int K) {
#pragma unroll
    for (int i = 0; i < 4; ++i) {
        int seg = tid + 256 * i, row = seg >> 3, s = seg & 7;
        const fp16* src = aHi + (size_t)(bM * 128 + row) * K + c * 64 + s * 8;
        cpasync16(sb + b * 16384 + swz(row * 128 + s * 16), src);
    }
#pragma unroll
    for (int i = 0; i < 4; ++i) {
        int seg = tid + 256 * i, hl = seg >> 9, rem = seg & 511, row = rem >> 3, s = rem & 7;
        const fp16* src = (hl ? bLo : bHi) + (size_t)(bJ * 64 + row) * K + c * 64 + s * 8;
        cpasync16(sb + 32768 + b * 16384 + hl * 8192 + swz(row * 128 + s * 16), src);
    }
}

template <int KDIM, int MODE>   // MODE 1: tanh(acc+bias)->g_hiA/g_loA; MODE 2: acc+bias->g_u
__global__ __launch_bounds__(256, 2) void k_mma64(
    const fp16* __restrict__ aHi,
    const fp16* __restrict__ bHi, const fp16* __restrict__ bLo,
    const float* __restrict__ bias)
{
    extern __shared__ char smem[];
    const int bJ = blockIdx.x, bM = blockIdx.y, tid = threadIdx.x;
    const int wid = tid >> 5, lane = tid & 31;
    const int mgrp = wid >> 2, ngrp = wid & 3;
    uint32_t sb = smem_u32(smem);
    const int NCH = KDIM / 64;

    float acc[4][2][4];
#pragma unroll
    for (int mt = 0; mt < 4; ++mt)
#pragma unroll
        for (int nt = 0; nt < 2; ++nt)
#pragma unroll
            for (int c = 0; c < 4; ++c) acc[mt][nt][c] = 0.f;

    mma64_copy(sb, 0, 0, bM, bJ, tid, aHi, bHi, bLo, KDIM);
    CP_COMMIT();

    for (int c = 0; c < NCH; ++c) {
        int b = c & 1;
        if (c + 1 < NCH) { mma64_copy(sb, c + 1, b ^ 1, bM, bJ, tid, aHi, bHi, bLo, KDIM);
                           CP_COMMIT(); CP_WAIT1(); }
        else CP_WAIT0();
        __syncthreads();
#pragma unroll
        for (int ks = 0; ks < 4; ++ks) {
            uint32_t aH[4][4], bH[4], bL[4];
#pragma unroll
            for (int mt = 0; mt < 4; ++mt) {
                int arow = mgrp * 64 + mt * 16 + (lane & 15);
                uint32_t off = swz(arow * 128 + ks * 32 + (lane >> 4) * 16);
                ldmx4(aH[mt], sb + b * 16384 + off);
            }
            int brow = ngrp * 16 + (lane & 7) + ((lane >> 4) & 1) * 8;
            uint32_t boff = swz(brow * 128 + ks * 32 + ((lane >> 3) & 1) * 16);
            ldmx4(bH, sb + 32768 + b * 16384 + boff);
            ldmx4(bL, sb + 32768 + b * 16384 + 8192 + boff);
#pragma unroll
            for (int mt = 0; mt < 4; ++mt)
#pragma unroll
                for (int nt = 0; nt < 2; ++nt)
                    mma_fp16(acc[mt][nt], aH[mt], bH + nt * 2);
#pragma unroll
            for (int mt = 0; mt < 4; ++mt)
#pragma unroll
                for (int nt = 0; nt < 2; ++nt)
                    mma_fp16(acc[mt][nt], aH[mt], bL + nt * 2);
        }
        __syncthreads();
    }

#pragma unroll
    for (int nt = 0; nt < 2; ++nt) {
        const int n = bJ * 64 + ngrp * 16 + nt * 8 + (lane & 3) * 2;
#pragma unroll
        for (int mt = 0; mt < 4; ++mt)
#pragma unroll
            for (int half = 0; half < 2; ++half) {
                int row = bM * 128 + mgrp * 64 + mt * 16 + (lane >> 2) + half * 8;
                if (MODE == 1) {
                    float hn0 = tanhf(acc[mt][nt][half * 2]     + bias[n]);
                    float hn1 = tanhf(acc[mt][nt][half * 2 + 1] + bias[n + 1]);
                    fp16 h0 = __float2half_rn(hn0), h1 = __float2half_rn(hn1);
                    __half2 hh; hh.x = h0; hh.y = h1;
                    __half2 ll;
                    ll.x = __float2half_rn(hn0 - __half2float(h0));
                    ll.y = __float2half_rn(hn1 - __half2float(h1));
                    *(__half2*)(g_hiA + (size_t)row * 512 + n) = hh;
                    *(__half2*)(g_loA + (size_t)row * 512 + n) = ll;
                } else {
                    *(float2*)(g_u + (size_t)row * 1024 + n) =
                        make_float2(acc[mt][nt][half * 2] + bias[n],
                                    acc[mt][nt][half * 2 + 1] + bias[n + 1]);
                }
            }
    }
}

// ================================== host ====================================
extern "C" void kernel_launch(void* const* d_in, const int* in_sizes, int n_in,
                              void* d_out, int out_size) {
    const float* z_q   = (const float*)d_in[0];
    const float* f_pr  = (const float*)d_in[1];
    const float* W1    = (const float*)d_in[2];
    const float* b1    = (const float*)d_in[3];
    const float* g1    = (const float*)d_in[4];
    const float* be1   = (const float*)d_in[5];
    const float* W2    = (const float*)d_in[6];
    const float* b2    = (const float*)d_in[7];
    const float* start = (const float*)d_in[8];
    const float* W_ih  = (const float*)d_in[9];
    const float* W_hh  = (const float*)d_in[10];
    const float* b_ih  = (const float*)d_in[11];
    const float* b_hh  = (const float*)d_in[12];
    const float* Wo1   = (const float*)d_in[13];
    const float* bo1   = (const float*)d_in[14];
    const float* go    = (const float*)d_in[15];
    const float* beo   = (const float*)d_in[16];
    const float* Wo2   = (const float*)d_in[17];
    const float* bo2   = (const float*)d_in[18];
    float* out = (float*)d_out;

    cudaFuncSetAttribute(k_gru_mma, cudaFuncAttributeMaxDynamicSharedMemorySize, GRU_SMEM);
    cudaFuncSetAttribute(k_outhead, cudaFuncAttributeMaxDynamicSharedMemorySize, OH_SMEM);
    cudaFuncSetAttribute(k_mma64<1024, 1>, cudaFuncAttributeMaxDynamicSharedMemorySize, MMA64_SMEM);
    cudaFuncSetAttribute(k_mma64<192, 2>, cudaFuncAttributeMaxDynamicSharedMemorySize, MMA64_SMEM);

    fp16 *cHiP, *uHiP, *w2HiP, *w2LoP, *w1HiP, *w1LoP;
    cudaGetSymbolAddress((void**)&cHiP, g_cHi);
    cudaGetSymbolAddress((void**)&uHiP, g_uHi);
    cudaGetSymbolAddress((void**)&w2HiP, g_W2Hi);
    cudaGetSymbolAddress((void**)&w2LoP, g_W2Lo);
    cudaGetSymbolAddress((void**)&w1HiP, g_W1Hi);
    cudaGetSymbolAddress((void**)&w1LoP, g_W1Lo);

    // weight prep
    k_cvtWhh<<<(1536 * 512 + 255) / 256, 256>>>(W_hh);
    k_splitWoT<<<(512 * 256 + 255) / 256, 256>>>(Wo1);
    k_splitW2T<<<(1024 * 512 + 255) / 256, 256>>>(W2);
    k_splitW1T<<<(1024 * 192 + 255) / 256, 256>>>(W1);

    // init MLP
    k_prep<<<(int)(((size_t)NR * 192 + 255) / 256), 256>>>(z_q, f_pr);
    k_mma64<192, 2><<<dim3(16, NR / 128), 256, MMA64_SMEM>>>(cHiP, w1HiP, w1LoP, b1);
    k_lngelu<<<NR, 256>>>(g1, be1);
    k_mma64<1024, 1><<<dim3(8, NR / 128), 256, MMA64_SMEM>>>(uHiP, w2HiP, w2LoP, b2);
    k_setx<<<NR / 256, 256>>>(start);

    // recurrence
    for (int t = 0; t < 20; ++t) {
        k_gru_mma<<<dim3(8, NR / 128), 512, GRU_SMEM>>>(W_ih, b_ih, b_hh, t);
        k_outhead<<<NR / 64, 256, OH_SMEM>>>(bo1, go, beo, Wo2, bo2, out, t);
    }
}

// round 16
// speedup vs baseline: 1.1066x; 1.0440x over previous
#include <cuda_runtime.h>
#include <cuda_fp16.h>
#include <cstdint>

#define NR 65536
typedef __half fp16;

// ----------------------------- device scratch ------------------------------
__device__ float g_u[(size_t)NR * 1024];
__device__ fp16  g_cHi[(size_t)NR * 192];    // concat(z,f) padded to K=192
__device__ fp16  g_uHi[(size_t)NR * 1024];
__device__ fp16  g_hiA[(size_t)NR * 512];
__device__ fp16  g_loA[(size_t)NR * 512];
__device__ fp16  g_hiB[(size_t)NR * 512];
__device__ fp16  g_loB[(size_t)NR * 512];
__device__ float g_x[NR];
__device__ fp16  g_WhhHi[1536 * 512];
__device__ fp16  g_Wo1Hi[256 * 512];     // transposed [N=256, K=512]
__device__ fp16  g_W2Hi[512 * 1024];     // transposed [N=512, K=1024]
__device__ fp16  g_W1Hi[1024 * 192];     // transposed+padded [N=1024, K=192]

// ----------------------------- small helpers -------------------------------
__device__ __forceinline__ float sig_(float x) { return 1.0f / (1.0f + expf(-x)); }
__device__ __forceinline__ float gelu_(float x) {
    return 0.5f * x * (1.0f + erff(x * 0.70710678f));
}
__device__ __forceinline__ uint32_t smem_u32(const void* p) {
    uint32_t a;
    asm("{ .reg .u64 t; cvta.to.shared.u64 t, %1; cvt.u32.u64 %0, t; }" : "=r"(a) : "l"(p));
    return a;
}
__device__ __forceinline__ uint32_t swz(uint32_t off) { return off ^ ((off >> 3) & 0x70); }

__device__ __forceinline__ void cpasync16(uint32_t saddr, const void* gptr) {
    asm volatile("{ .reg .u64 g; cvta.to.global.u64 g, %1; "
                 "cp.async.cg.shared.global [%0], [g], 16; }"
                 :: "r"(saddr), "l"(gptr) : "memory");
}
#define CP_COMMIT() asm volatile("cp.async.commit_group;" ::: "memory")
#define CP_WAIT1()  asm volatile("cp.async.wait_group 1;" ::: "memory")
#define CP_WAIT0()  asm volatile("cp.async.wait_group 0;" ::: "memory")

__device__ __forceinline__ void ldmx4(uint32_t* r, uint32_t addr) {
    asm volatile("ldmatrix.sync.aligned.m8n8.x4.shared.b16 {%0,%1,%2,%3}, [%4];"
        : "=r"(r[0]), "=r"(r[1]), "=r"(r[2]), "=r"(r[3]) : "r"(addr));
}
__device__ __forceinline__ void mma_fp16(float* d, const uint32_t* a, const uint32_t* b) {
    asm volatile("mma.sync.aligned.m16n8k16.row.col.f32.f16.f16.f32 "
        "{%0,%1,%2,%3}, {%4,%5,%6,%7}, {%8,%9}, {%0,%1,%2,%3};"
        : "+f"(d[0]), "+f"(d[1]), "+f"(d[2]), "+f"(d[3])
        : "r"(a[0]), "r"(a[1]), "r"(a[2]), "r"(a[3]), "r"(b[0]), "r"(b[1]));
}

// =========================== init-path kernels =============================
__global__ void k_prep(const float* __restrict__ z, const float* __restrict__ f) {
    size_t i = (size_t)blockIdx.x * blockDim.x + threadIdx.x;
    if (i >= (size_t)NR * 192) return;
    int row = (int)(i / 192), col = (int)(i % 192);
    float x = (col < 128) ? z[(size_t)row * 128 + col]
            : (col < 160) ? f[(size_t)row * 32 + col - 128] : 0.f;
    g_cHi[i] = __float2half_rn(x);
}

__global__ __launch_bounds__(256) void k_lngelu(
    const float* __restrict__ g1, const float* __restrict__ be1)
{
    const size_t row = blockIdx.x;
    const int tid = threadIdx.x, lane = tid & 31, w = tid >> 5;
    const float* up = g_u + row * 1024 + tid * 4;
    float4 v = *(const float4*)up;
    __shared__ float red[8];
    float s = v.x + v.y + v.z + v.w;
#pragma unroll
    for (int m = 16; m >= 1; m >>= 1) s += __shfl_xor_sync(~0u, s, m);
    if (lane == 0) red[w] = s;
    __syncthreads();
    float tot = 0.f;
#pragma unroll
    for (int i = 0; i < 8; ++i) tot += red[i];
    const float mean = tot * (1.0f / 1024.0f);
    float dx = v.x - mean, dy = v.y - mean, dz = v.z - mean, dw = v.w - mean;
    float q = dx * dx + dy * dy + dz * dz + dw * dw;
#pragma unroll
    for (int m = 16; m >= 1; m >>= 1) q += __shfl_xor_sync(~0u, q, m);
    __syncthreads();
    if (lane == 0) red[w] = q;
    __syncthreads();
    float qt = 0.f;
#pragma unroll
    for (int i = 0; i < 8; ++i) qt += red[i];
    const float rstd = rsqrtf(qt * (1.0f / 1024.0f) + 1e-5f);
    const int j = tid * 4;
    float4 g4 = *(const float4*)&g1[j];
    float4 b4 = *(const float4*)&be1[j];
    __align__(8) fp16 hb[4];
    hb[0] = __float2half_rn(gelu_(dx * rstd * g4.x + b4.x));
    hb[1] = __float2half_rn(gelu_(dy * rstd * g4.y + b4.y));
    hb[2] = __float2half_rn(gelu_(dz * rstd * g4.z + b4.z));
    hb[3] = __float2half_rn(gelu_(dw * rstd * g4.w + b4.w));
    *(uint2*)(g_uHi + row * 1024 + j) = *(uint2*)hb;
}

__global__ void k_setx(const float* __restrict__ st) {
    int i = blockIdx.x * blockDim.x + threadIdx.x;
    if (i < NR) g_x[i] = st[0];
}

// -------- weight prep (hi planes only) --------
__global__ void k_cvtWhh(const float* __restrict__ W_hh) {
    int i = blockIdx.x * blockDim.x + threadIdx.x;
    if (i >= 1536 * 512) return;
    g_WhhHi[i] = __float2half_rn(W_hh[i]);
}
__global__ void k_cvtWoT(const float* __restrict__ Wo1) {
    int i = blockIdx.x * blockDim.x + threadIdx.x;
    if (i >= 512 * 256) return;
    int k = i >> 8, n = i & 255;
    g_Wo1Hi[n * 512 + k] = __float2half_rn(Wo1[i]);
}
__global__ void k_cvtW2T(const float* __restrict__ W2) {
    int i = blockIdx.x * blockDim.x + threadIdx.x;
    if (i >= 1024 * 512) return;
    int k = i >> 9, n = i & 511;
    g_W2Hi[n * 1024 + k] = __float2half_rn(W2[i]);
}
__global__ void k_cvtW1T(const float* __restrict__ W1) {
    int i = blockIdx.x * blockDim.x + threadIdx.x;
    if (i >= 1024 * 192) return;
    int n = i / 192, k = i % 192;
    float x = (k < 160) ? W1[(size_t)k * 1024 + n] : 0.f;
    g_W1Hi[i] = __float2half_rn(x);
}

// ============================ GRU step (mma.sync) ===========================
// R13 tiling, but 2-chunk commit groups with 4 smem slots: syncs 16 -> 8.
// A slots @ slot*16384 (4x16KB); B slots @ 65536 + slot*24576 (4x24KB). 160KB.
#define GRU_SMEM (160 * 1024)

__device__ __forceinline__ void gru_copy(uint32_t sb, int c, int bM, int bJ,
                                         int tid, const fp16* hiIn) {
    const int slot = c & 3;
#pragma unroll
    for (int i = 0; i < 2; ++i) {            // A: 1024 segs of 16B
        int seg = tid + 512 * i, row = seg >> 3, s = seg & 7;
        const fp16* src = hiIn + (size_t)(bM * 128 + row) * 512 + c * 64 + s * 8;
        cpasync16(sb + slot * 16384 + swz(row * 128 + s * 16), src);
    }
#pragma unroll
    for (int i = 0; i < 3; ++i) {            // B: 1536 segs of 16B (192 rows)
        int seg = tid + 512 * i, row = seg >> 3, s = seg & 7;
        int grow = (row >> 6) * 512 + bJ * 64 + (row & 63);
        const fp16* src = g_WhhHi + (size_t)grow * 512 + c * 64 + s * 8;
        cpasync16(sb + 65536 + slot * 24576 + swz(row * 128 + s * 16), src);
    }
}

__global__ __launch_bounds__(512, 1) void k_gru_mma(
    const float* __restrict__ W_ih, const float* __restrict__ b_ih,
    const float* __restrict__ b_hh, int t)
{
    extern __shared__ char smem[];
    const fp16* hiIn  = (t & 1) ? g_hiB : g_hiA;
    const fp16* loIn  = (t & 1) ? g_loB : g_loA;
    fp16*       hiOut = (t & 1) ? g_hiA : g_hiB;
    fp16*       loOut = (t & 1) ? g_loA : g_loB;

    const int bJ = blockIdx.x, bM = blockIdx.y, tid = threadIdx.x;
    const int wid = tid >> 5, lane = tid & 31;
    const int mgrp = wid >> 2, ngrp = wid & 3;
    uint32_t sb = smem_u32(smem);

    float acc[3][2][2][4];
#pragma unroll
    for (int g = 0; g < 3; ++g)
#pragma unroll
        for (int mt = 0; mt < 2; ++mt)
#pragma unroll
            for (int nt = 0; nt < 2; ++nt)
#pragma unroll
                for (int c = 0; c < 4; ++c) acc[g][mt][nt][c] = 0.f;

    gru_copy(sb, 0, bM, bJ, tid, hiIn);
    gru_copy(sb, 1, bM, bJ, tid, hiIn);
    CP_COMMIT();

    for (int c = 0; c < 8; c += 2) {
        if (c + 2 < 8) {
            gru_copy(sb, c + 2, bM, bJ, tid, hiIn);
            gru_copy(sb, c + 3, bM, bJ, tid, hiIn);
            CP_COMMIT(); CP_WAIT1();
        } else CP_WAIT0();
        __syncthreads();
#pragma unroll
        for (int u = 0; u < 2; ++u) {
            const int slot = (c + u) & 3;
            const uint32_t aBase = sb + slot * 16384;
            const uint32_t bBase = sb + 65536 + slot * 24576;
#pragma unroll
            for (int ks = 0; ks < 4; ++ks) {
                uint32_t aH[2][4], bH[3][4];
#pragma unroll
                for (int mt = 0; mt < 2; ++mt) {
                    int arow = mgrp * 32 + mt * 16 + (lane & 15);
                    uint32_t off = swz(arow * 128 + ks * 32 + (lane >> 4) * 16);
                    ldmx4(aH[mt], aBase + off);
                }
#pragma unroll
                for (int g = 0; g < 3; ++g) {
                    int brow = g * 64 + ngrp * 16 + (lane & 7) + ((lane >> 4) & 1) * 8;
                    uint32_t boff = swz(brow * 128 + ks * 32 + ((lane >> 3) & 1) * 16);
                    ldmx4(bH[g], bBase + boff);
                }
#pragma unroll
                for (int g = 0; g < 3; ++g)
#pragma unroll
                    for (int mt = 0; mt < 2; ++mt)
#pragma unroll
                        for (int nt = 0; nt < 2; ++nt)
                            mma_fp16(acc[g][mt][nt], aH[mt], bH[g] + nt * 2);
            }
        }
        __syncthreads();
    }

    // ---- in-register gate epilogue (h_old reconstructed from hi/lo) ----
#pragma unroll
    for (int nt = 0; nt < 2; ++nt) {
        const int j = bJ * 64 + ngrp * 16 + nt * 8 + (lane & 3) * 2;
        float wih[3][2], bih[3][2], bhh[3][2];
#pragma unroll
        for (int g = 0; g < 3; ++g)
#pragma unroll
            for (int cc = 0; cc < 2; ++cc) {
                wih[g][cc] = W_ih[g * 512 + j + cc];
                bih[g][cc] = b_ih[g * 512 + j + cc];
                bhh[g][cc] = b_hh[g * 512 + j + cc];
            }
#pragma unroll
        for (int mt = 0; mt < 2; ++mt)
#pragma unroll
            for (int half = 0; half < 2; ++half) {
                int row = bM * 128 + mgrp * 32 + mt * 16 + (lane >> 2) + half * 8;
                float xi = g_x[row];
                __half2 h2 = *(const __half2*)(hiIn + (size_t)row * 512 + j);
                __half2 l2 = *(const __half2*)(loIn + (size_t)row * 512 + j);
                float hOld[2] = { __half2float(h2.x) + __half2float(l2.x),
                                  __half2float(h2.y) + __half2float(l2.y) };
                float hn[2];
#pragma unroll
                for (int cc = 0; cc < 2; ++cc) {
                    float ghr = acc[0][mt][nt][half * 2 + cc];
                    float ghz = acc[1][mt][nt][half * 2 + cc];
                    float ghn = acc[2][mt][nt][half * 2 + cc];
                    float rr = sig_(fmaf(xi, wih[0][cc], bih[0][cc]) + ghr + bhh[0][cc]);
                    float zz = sig_(fmaf(xi, wih[1][cc], bih[1][cc]) + ghz + bhh[1][cc]);
                    float nn = tanhf(fmaf(xi, wih[2][cc], bih[2][cc]) + rr * (ghn + bhh[2][cc]));
                    hn[cc] = (1.0f - zz) * nn + zz * hOld[cc];
                }
                fp16 h0 = __float2half_rn(hn[0]), h1 = __float2half_rn(hn[1]);
                __half2 hh; hh.x = h0; hh.y = h1;
                __half2 ll;
                ll.x = __float2half_rn(hn[0] - __half2float(h0));
                ll.y = __float2half_rn(hn[1] - __half2float(h1));
                *(__half2*)(hiOut + (size_t)row * 512 + j) = hh;
                *(__half2*)(loOut + (size_t)row * 512 + j) = ll;
            }
    }
}

// ====== fused output head: 64-row blocks, register-resident LN =============
// R15 version unchanged. 256 threads, SMEM 83456 -> 2 CTAs/SM.
#define OH_SMEM 83456

__device__ __forceinline__ void oh_copy(uint32_t sb, int c, int b, int bM,
                                        int tid, const fp16* hiIn) {
#pragma unroll
    for (int i = 0; i < 2; ++i) {            // A: 512 segs (64 rows)
        int seg = tid + 256 * i, row = seg >> 3, s = seg & 7;
        const fp16* src = hiIn + (size_t)(bM * 64 + row) * 512 + c * 64 + s * 8;
        cpasync16(sb + b * 8192 + swz(row * 128 + s * 16), src);
    }
#pragma unroll
    for (int i = 0; i < 8; ++i) {            // B: 2048 segs (256 rows)
        int seg = tid + 256 * i, row = seg >> 3, s = seg & 7;
        const fp16* src = g_Wo1Hi + (size_t)row * 512 + c * 64 + s * 8;
        cpasync16(sb + 16384 + b * 32768 + swz(row * 128 + s * 16), src);
    }
}

__global__ __launch_bounds__(256, 2) void k_outhead(
    const float* __restrict__ bo1, const float* __restrict__ go,
    const float* __restrict__ beo, const float* __restrict__ Wo2,
    const float* __restrict__ bo2, float* __restrict__ out, int t)
{
    extern __shared__ char smem[];
    const fp16* hiIn = (t & 1) ? g_hiA : g_hiB;   // h_new from gru(t)
    const int bM = blockIdx.x, tid = threadIdx.x;
    const int wid = tid >> 5, lane = tid & 31;
    const int mgrp = wid >> 2, ngrp = wid & 3;
    uint32_t sb = smem_u32(smem);

    float acc[2][8][4];
#pragma unroll
    for (int mt = 0; mt < 2; ++mt)
#pragma unroll
        for (int n8 = 0; n8 < 8; ++n8)
#pragma unroll
            for (int c = 0; c < 4; ++c) acc[mt][n8][c] = 0.f;

    oh_copy(sb, 0, 0, bM, tid, hiIn);
    CP_COMMIT();

    for (int c = 0; c < 8; ++c) {
        int b = c & 1;
        if (c + 1 < 8) { oh_copy(sb, c + 1, b ^ 1, bM, tid, hiIn); CP_COMMIT(); CP_WAIT1(); }
        else CP_WAIT0();
        __syncthreads();
#pragma unroll
        for (int ks = 0; ks < 4; ++ks) {
            uint32_t aH[2][4];
#pragma unroll
            for (int mt = 0; mt < 2; ++mt) {
                int arow = mgrp * 32 + mt * 16 + (lane & 15);
                uint32_t off = swz(arow * 128 + ks * 32 + (lane >> 4) * 16);
                ldmx4(aH[mt], sb + b * 8192 + off);
            }
#pragma unroll
            for (int g16 = 0; g16 < 4; ++g16) {
                int brow = ngrp * 64 + g16 * 16 + (lane & 7) + ((lane >> 4) & 1) * 8;
                uint32_t boff = swz(brow * 128 + ks * 32 + ((lane >> 3) & 1) * 16);
                uint32_t bB[4];
                ldmx4(bB, sb + 16384 + b * 32768 + boff);
#pragma unroll
                for (int mt = 0; mt < 2; ++mt)
#pragma unroll
                    for (int nt = 0; nt < 2; ++nt)
                        mma_fp16(acc[mt][g16 * 2 + nt], aH[mt], bB + nt * 2);
            }
        }
        __syncthreads();
    }

    // ---- register-resident LN + GELU + dot via partial reductions ----
    float* red   = (float*)(smem + 81920);    // [64][4]
    float* meanv = (float*)(smem + 82944);    // [64]
    float* rstdv = (float*)(smem + 83200);    // [64]

    float bo1v[8][2];
#pragma unroll
    for (int n8 = 0; n8 < 8; ++n8)
#pragma unroll
        for (int cc = 0; cc < 2; ++cc)
            bo1v[n8][cc] = bo1[ngrp * 64 + n8 * 8 + (lane & 3) * 2 + cc];

    // pass 1: row sums
#pragma unroll
    for (int mt = 0; mt < 2; ++mt)
#pragma unroll
        for (int half = 0; half < 2; ++half) {
            int row_l = mgrp * 32 + mt * 16 + (lane >> 2) + half * 8;
            float s = 0.f;
#pragma unroll
            for (int n8 = 0; n8 < 8; ++n8)
#pragma unroll
                for (int cc = 0; cc < 2; ++cc)
                    s += acc[mt][n8][half * 2 + cc] + bo1v[n8][cc];
            s += __shfl_xor_sync(~0u, s, 1);
            s += __shfl_xor_sync(~0u, s, 2);
            if ((lane & 3) == 0) red[row_l * 4 + ngrp] = s;
        }
    __syncthreads();
    if (tid < 64)
        meanv[tid] = (red[tid * 4] + red[tid * 4 + 1] + red[tid * 4 + 2] + red[tid * 4 + 3])
                     * (1.0f / 256.0f);
    __syncthreads();

    // pass 2: variance
#pragma unroll
    for (int mt = 0; mt < 2; ++mt)
#pragma unroll
        for (int half = 0; half < 2; ++half) {
            int row_l = mgrp * 32 + mt * 16 + (lane >> 2) + half * 8;
            float mu = meanv[row_l];
            float q = 0.f;
#pragma unroll
            for (int n8 = 0; n8 < 8; ++n8)
#pragma unroll
                for (int cc = 0; cc < 2; ++cc) {
                    float d = acc[mt][n8][half * 2 + cc] + bo1v[n8][cc] - mu;
                    q += d * d;
                }
            q += __shfl_xor_sync(~0u, q, 1);
            q += __shfl_xor_sync(~0u, q, 2);
            if ((lane & 3) == 0) red[row_l * 4 + ngrp] = q;
        }
    __syncthreads();
    if (tid < 64)
        rstdv[tid] = rsqrtf((red[tid * 4] + red[tid * 4 + 1] + red[tid * 4 + 2] + red[tid * 4 + 3])
                            * (1.0f / 256.0f) + 1e-5f);
    __syncthreads();

    // pass 3: y partials
    {
        float mu[2][2], rs[2][2];
#pragma unroll
        for (int mt = 0; mt < 2; ++mt)
#pragma unroll
            for (int half = 0; half < 2; ++half) {
                int row_l = mgrp * 32 + mt * 16 + (lane >> 2) + half * 8;
                mu[mt][half] = meanv[row_l];
                rs[mt][half] = rstdv[row_l];
            }
        float yp[2][2] = {{0.f, 0.f}, {0.f, 0.f}};
#pragma unroll
        for (int n8 = 0; n8 < 8; ++n8) {
#pragma unroll
            for (int cc = 0; cc < 2; ++cc) {
                int col = ngrp * 64 + n8 * 8 + (lane & 3) * 2 + cc;
                float gv = go[col], bv = beo[col], wv = Wo2[col];
#pragma unroll
                for (int mt = 0; mt < 2; ++mt)
#pragma unroll
                    for (int half = 0; half < 2; ++half) {
                        float v = acc[mt][n8][half * 2 + cc] + bo1v[n8][cc];
                        float ln = (v - mu[mt][half]) * rs[mt][half] * gv + bv;
                        yp[mt][half] += gelu_(ln) * wv;
                    }
            }
        }
        __syncthreads();   // red reuse
#pragma unroll
        for (int mt = 0; mt < 2; ++mt)
#pragma unroll
            for (int half = 0; half < 2; ++half) {
                int row_l = mgrp * 32 + mt * 16 + (lane >> 2) + half * 8;
                float y = yp[mt][half];
                y += __shfl_xor_sync(~0u, y, 1);
                y += __shfl_xor_sync(~0u, y, 2);
                if ((lane & 3) == 0) red[row_l * 4 + ngrp] = y;
            }
    }
    __syncthreads();
    if (tid < 64) {
        float yy = red[tid * 4] + red[tid * 4 + 1] + red[tid * 4 + 2] + red[tid * 4 + 3] + bo2[0];
        int row = bM * 64 + tid;
        out[(size_t)row * 20 + t] = yy;
        g_x[row] = yy;
    }
}

// ======== generic 128-row x 64-col fp16 1-term mma GEMM (init only) =========
#define MMA64_SMEM (48 * 1024)

__device__ __forceinline__ void mma64_copy(uint32_t sb, int c, int b, int bM, int bJ,
                                           int tid, const fp16* aHi,
                                           const fp16* bHi, int K) {
#pragma unroll
    for (int i = 0; i < 4; ++i) {            // A: 1024 segs
        int seg = tid + 256 * i, row = seg >> 3, s = seg & 7;
        const fp16* src = aHi + (size_t)(bM * 128 + row) * K + c * 64 + s * 8;
        cpasync16(sb + b * 16384 + swz(row * 128 + s * 16), src);
    }
#pragma unroll
    for (int i = 0; i < 2; ++i) {            // B: 512 segs (64 rows)
        int seg = tid + 256 * i, row = seg >> 3, s = seg & 7;
        const fp16* src = bHi + (size_t)(bJ * 64 + row) * K + c * 64 + s * 8;
        cpasync16(sb + 32768 + b * 8192 + swz(row * 128 + s * 16), src);
    }
}

template <int KDIM, int MODE>   // MODE 1: tanh(acc+bias)->g_hiA/g_loA; MODE 2: acc+bias->g_u
__global__ __launch_bounds__(256, 2) void k_mma64(
    const fp16* __restrict__ aHi, const fp16* __restrict__ bHi,
    const float* __restrict__ bias)
{
    extern __shared__ char smem[];
    const int bJ = blockIdx.x, bM = blockIdx.y, tid = threadIdx.x;
    const int wid = tid >> 5, lane = tid & 31;
    const int mgrp = wid >> 2, ngrp = wid & 3;
    uint32_t sb = smem_u32(smem);
    const int NCH = KDIM / 64;

    float acc[4][2][4];
#pragma unroll
    for (int mt = 0; mt < 4; ++mt)
#pragma unroll
        for (int nt = 0; nt < 2; ++nt)
#pragma unroll
            for (int c = 0; c < 4; ++c) acc[mt][nt][c] = 0.f;

    mma64_copy(sb, 0, 0, bM, bJ, tid, aHi, bHi, KDIM);
    CP_COMMIT();

    for (int c = 0; c < NCH; ++c) {
        int b = c & 1;
        if (c + 1 < NCH) { mma64_copy(sb, c + 1, b ^ 1, bM, bJ, tid, aHi, bHi, KDIM);
                           CP_COMMIT(); CP_WAIT1(); }
        else CP_WAIT0();
        __syncthreads();
#pragma unroll
        for (int ks = 0; ks < 4; ++ks) {
            uint32_t aH[4][4], bH[4];
#pragma unroll
            for (int mt = 0; mt < 4; ++mt) {
                int arow = mgrp * 64 + mt * 16 + (lane & 15);
                uint32_t off = swz(arow * 128 + ks * 32 + (lane >> 4) * 16);
                ldmx4(aH[mt], sb + b * 16384 + off);
            }
            int brow = ngrp * 16 + (lane & 7) + ((lane >> 4) & 1) * 8;
            uint32_t boff = swz(brow * 128 + ks * 32 + ((lane >> 3) & 1) * 16);
            ldmx4(bH, sb + 32768 + b * 8192 + boff);
#pragma unroll
            for (int mt = 0; mt < 4; ++mt)
#pragma unroll
                for (int nt = 0; nt < 2; ++nt)
                    mma_fp16(acc[mt][nt], aH[mt], bH + nt * 2);
        }
        __syncthreads();
    }

#pragma unroll
    for (int nt = 0; nt < 2; ++nt) {
        const int n = bJ * 64 + ngrp * 16 + nt * 8 + (lane & 3) * 2;
#pragma unroll
        for (int mt = 0; mt < 4; ++mt)
#pragma unroll
            for (int half = 0; half < 2; ++half) {
                int row = bM * 128 + mgrp * 64 + mt * 16 + (lane >> 2) + half * 8;
                if (MODE == 1) {
                    float hn0 = tanhf(acc[mt][nt][half * 2]     + bias[n]);
                    float hn1 = tanhf(acc[mt][nt][half * 2 + 1] + bias[n + 1]);
                    fp16 h0 = __float2half_rn(hn0), h1 = __float2half_rn(hn1);
                    __half2 hh; hh.x = h0; hh.y = h1;
                    __half2 ll;
                    ll.x = __float2half_rn(hn0 - __half2float(h0));
                    ll.y = __float2half_rn(hn1 - __half2float(h1));
                    *(__half2*)(g_hiA + (size_t)row * 512 + n) = hh;
                    *(__half2*)(g_loA + (size_t)row * 512 + n) = ll;
                } else {
                    *(float2*)(g_u + (size_t)row * 1024 + n) =
                        make_float2(acc[mt][nt][half * 2] + bias[n],
                                    acc[mt][nt][half * 2 + 1] + bias[n + 1]);
                }
            }
    }
}

// ================================== host ====================================
extern "C" void kernel_launch(void* const* d_in, const int* in_sizes, int n_in,
                              void* d_out, int out_size) {
    const float* z_q   = (const float*)d_in[0];
    const float* f_pr  = (const float*)d_in[1];
    const float* W1    = (const float*)d_in[2];
    const float* b1    = (const float*)d_in[3];
    const float* g1    = (const float*)d_in[4];
    const float* be1   = (const float*)d_in[5];
    const float* W2    = (const float*)d_in[6];
    const float* b2    = (const float*)d_in[7];
    const float* start = (const float*)d_in[8];
    const float* W_ih  = (const float*)d_in[9];
    const float* W_hh  = (const float*)d_in[10];
    const float* b_ih  = (const float*)d_in[11];
    const float* b_hh  = (const float*)d_in[12];
    const float* Wo1   = (const float*)d_in[13];
    const float* bo1   = (const float*)d_in[14];
    const float* go    = (const float*)d_in[15];
    const float* beo   = (const float*)d_in[16];
    const float* Wo2   = (const float*)d_in[17];
    const float* bo2   = (const float*)d_in[18];
    float* out = (float*)d_out;

    cudaFuncSetAttribute(k_gru_mma, cudaFuncAttributeMaxDynamicSharedMemorySize, GRU_SMEM);
    cudaFuncSetAttribute(k_outhead, cudaFuncAttributeMaxDynamicSharedMemorySize, OH_SMEM);
    cudaFuncSetAttribute(k_mma64<1024, 1>, cudaFuncAttributeMaxDynamicSharedMemorySize, MMA64_SMEM);
    cudaFuncSetAttribute(k_mma64<192, 2>, cudaFuncAttributeMaxDynamicSharedMemorySize, MMA64_SMEM);

    fp16 *cHiP, *uHiP, *w2HiP, *w1HiP;
    cudaGetSymbolAddress((void**)&cHiP, g_cHi);
    cudaGetSymbolAddress((void**)&uHiP, g_uHi);
    cudaGetSymbolAddress((void**)&w2HiP, g_W2Hi);
    cudaGetSymbolAddress((void**)&w1HiP, g_W1Hi);

    // weight prep
    k_cvtWhh<<<(1536 * 512 + 255) / 256, 256>>>(W_hh);
    k_cvtWoT<<<(512 * 256 + 255) / 256, 256>>>(Wo1);
    k_cvtW2T<<<(1024 * 512 + 255) / 256, 256>>>(W2);
    k_cvtW1T<<<(1024 * 192 + 255) / 256, 256>>>(W1);

    // init MLP
    k_prep<<<(int)(((size_t)NR * 192 + 255) / 256), 256>>>(z_q, f_pr);
    k_mma64<192, 2><<<dim3(16, NR / 128), 256, MMA64_SMEM>>>(cHiP, w1HiP, b1);
    k_lngelu<<<NR, 256>>>(g1, be1);
    k_mma64<1024, 1><<<dim3(8, NR / 128), 256, MMA64_SMEM>>>(uHiP, w2HiP, b2);
    k_setx<<<NR / 256, 256>>>(start);

    // recurrence
    for (int t = 0; t < 20; ++t) {
        k_gru_mma<<<dim3(8, NR / 128), 512, GRU_SMEM>>>(W_ih, b_ih, b_hh, t);
        k_outhead<<<NR / 64, 256, OH_SMEM>>>(bo1, go, beo, Wo2, bo2, out, t);
    }
}